// round 1
// baseline (speedup 1.0000x reference)
#include <cuda_runtime.h>
#include <math.h>

#define NFFT 512
#define HOP  128
#define PAD  256
#define LSIG 160000
#define BB   16
#define CC   4
#define TT   1251
#define FDIM 257
#define KFEAT (4 * CC * FDIM)   // 4112
#define CF   (CC * FDIM)        // 1028

#define PI_D 3.14159265358979323846

// steering-vector table: [0..CF) = cos(phase)/2, [CF..2CF) = sin(phase)/2
__device__ float g_sv[2 * CF];

// ---------------------------------------------------------------------------
// Prep: TDOA (summed over batch AND coord, per reference) + sv table
// ---------------------------------------------------------------------------
__global__ void prep_kernel(const float* __restrict__ angle,
                            const float* __restrict__ mic_pos) {
    __shared__ float tdoa[CC];
    int tid = threadIdx.x;
    if (tid < CC) {
        const float half_pi = (float)(PI_D / 2.0);
        float sin90 = sinf(half_pi);   // ~1.0f (fp32 quirk reproduced)
        float cos90 = cosf(half_pi);   // ~-4.4e-8f
        float sum = 0.f;
        for (int b = 0; b < BB; b++) {
            float rad = -angle[b] * (float)(PI_D / 180.0);
            float lx = cosf(rad) * sin90;
            float ly = sinf(rad) * sin90;
            float lz = cos90;          // DIST = 1.0
            const float* mp = mic_pos + (b * CC + tid) * 3;
            float dx = mp[0] - lx, dy = mp[1] - ly, dz = mp[2] - lz;
            sum += dx * dx + dy * dy + dz * dz;
        }
        tdoa[tid] = sqrtf(sum);
    }
    __syncthreads();
    const float d0 = tdoa[0];
    const float coef = (float)(-2.0 * PI_D * 16000.0 / (512.0 * 340.4));
    for (int i = tid; i < CF; i += blockDim.x) {
        int c = i / FDIM;
        int f = i - c * FDIM;
        float ph = coef * (float)f * (tdoa[c] - d0);
        float s, co;
        sincosf(ph, &s, &co);
        g_sv[i]      = co * 0.5f;   // sv.real / ||sv||  (norm = sqrt(C) = 2)
        g_sv[CF + i] = s * 0.5f;    // sv.imag / 2
    }
}

// ---------------------------------------------------------------------------
// STFT: one block = one frame. 512-pt radix-2 complex FFT in shared memory.
// Writes X.real -> feature group 0, X.imag -> group 1.
// ---------------------------------------------------------------------------
__global__ void __launch_bounds__(256) stft_kernel(const float* __restrict__ x,
                                                   float* __restrict__ out) {
    __shared__ float sr[NFFT], si[NFFT];
    __shared__ float twr[NFFT / 2], twi[NFFT / 2];

    const int t   = blockIdx.x;   // frame
    const int bc  = blockIdx.y;   // b*C + c
    const int tid = threadIdx.x;  // 256 threads

    // per-block twiddle table: w[k] = exp(-2*pi*i*k/512), k = 0..255
    {
        float ang = (float)(-2.0 * PI_D / (double)NFFT) * (float)tid;
        float s, c;
        sincosf(ang, &s, &c);
        twr[tid] = c;
        twi[tid] = s;
    }

    // load 2 windowed samples each, bit-reversed into shared
    const float* xs = x + (size_t)bc * LSIG;
#pragma unroll
    for (int u = 0; u < 2; u++) {
        int n = tid + u * 256;
        int p = t * HOP + n - PAD;                    // reflect pad index
        int s = (p < 0) ? -p : ((p >= LSIG) ? (2 * LSIG - 2 - p) : p);
        float w = 0.5f * (1.0f - cosf((float)(2.0 * PI_D / (double)NFFT) * (float)n));
        int r = (int)(__brev((unsigned)n) >> 23);     // 9-bit reversal
        sr[r] = xs[s] * w;
        si[r] = 0.f;
    }
    __syncthreads();

    // 9 radix-2 DIT stages; 256 butterflies per stage, 1 per thread
#pragma unroll
    for (int st = 1; st <= 9; st++) {
        int half = 1 << (st - 1);
        int j    = tid & (half - 1);
        int i0   = ((tid >> (st - 1)) << st) + j;
        int i1   = i0 + half;
        int twk  = j << (9 - st);
        float cw = twr[twk], sw = twi[twk];
        float br = sr[i1], bi = si[i1];
        float tr = br * cw - bi * sw;
        float ti = br * sw + bi * cw;
        float ar = sr[i0], ai = si[i0];
        sr[i0] = ar + tr; si[i0] = ai + ti;
        sr[i1] = ar - tr; si[i1] = ai - ti;
        __syncthreads();
    }

    // write X.real (group 0) and X.imag (group 1); rfft = first 257 bins
    const int b = bc >> 2;
    const int c = bc & 3;
    float* o = out + ((size_t)b * TT + t) * KFEAT + c * FDIM;
    for (int k = tid; k < FDIM; k += 256) {
        o[k]      = sr[k];
        o[CF + k] = si[k];
    }
}

// ---------------------------------------------------------------------------
// SV broadcast: groups 2 (sv.real) and 3 (sv.imag), constant over t
// ---------------------------------------------------------------------------
__global__ void __launch_bounds__(256) sv_kernel(float* __restrict__ out) {
    float* o = out + (size_t)blockIdx.x * KFEAT + 2 * CF;
    for (int i = threadIdx.x; i < 2 * CF; i += blockDim.x) {
        o[i] = g_sv[i];
    }
}

// ---------------------------------------------------------------------------
extern "C" void kernel_launch(void* const* d_in, const int* in_sizes, int n_in,
                              void* d_out, int out_size) {
    const float* x     = (const float*)d_in[0];
    const float* angle = (const float*)d_in[1];
    const float* mic   = (const float*)d_in[2];
    float* out = (float*)d_out;

    prep_kernel<<<1, 256>>>(angle, mic);

    dim3 grid(TT, BB * CC);
    stft_kernel<<<grid, 256>>>(x, out);

    sv_kernel<<<BB * TT, 256>>>(out);
}

// round 2
// speedup vs baseline: 4.6879x; 4.6879x over previous
#include <cuda_runtime.h>
#include <math.h>

#define NFFT 512
#define HOP  128
#define LSIG 160000
#define BB   16
#define CC   4
#define TT   1251
#define FDIM 257
#define KFEAT (4 * CC * FDIM)   // 4112
#define CF   (CC * FDIM)        // 1028

#define PI_D 3.14159265358979323846

struct c2 { float x, y; };

__device__ __forceinline__ c2 cmul(c2 a, c2 b){ c2 r; r.x = a.x*b.x - a.y*b.y; r.y = a.x*b.y + a.y*b.x; return r; }
__device__ __forceinline__ c2 cadd(c2 a, c2 b){ c2 r; r.x = a.x+b.x; r.y = a.y+b.y; return r; }
__device__ __forceinline__ c2 csub(c2 a, c2 b){ c2 r; r.x = a.x-b.x; r.y = a.y-b.y; return r; }
__device__ __forceinline__ c2 mulnegi(c2 a){ c2 r; r.x = a.y; r.y = -a.x; return r; }   // a * (-i)

// radix-8 DFT: o[k] = sum_j v[j] * w8^{j*k}, w8 = exp(-2*pi*i/8)
__device__ __forceinline__ void radix8(const c2* v, c2* o) {
    const float S = 0.70710678118654752f;
    c2 a0=cadd(v[0],v[4]), a1=csub(v[0],v[4]);
    c2 a2=cadd(v[2],v[6]), a3=csub(v[2],v[6]);
    c2 b0=cadd(v[1],v[5]), b1=csub(v[1],v[5]);
    c2 b2=cadd(v[3],v[7]), b3=csub(v[3],v[7]);
    c2 ia3 = mulnegi(a3), ib3 = mulnegi(b3);
    c2 c0=cadd(a0,a2), c1=csub(a0,a2);
    c2 e2=cadd(a1,ia3), e3=csub(a1,ia3);
    c2 d0=cadd(b0,b2), d1=csub(b0,b2);
    c2 d2=cadd(b1,ib3), d3=csub(b1,ib3);
    c2 w1d2; w1d2.x = S*(d2.x + d2.y); w1d2.y = S*(d2.y - d2.x);   // (S - iS)*d2
    c2 w3d3; w3d3.x = S*(d3.y - d3.x); w3d3.y = -S*(d3.x + d3.y);  // (-S - iS)*d3
    c2 id1 = mulnegi(d1);
    o[0]=cadd(c0,d0);    o[4]=csub(c0,d0);
    o[2]=cadd(c1,id1);   o[6]=csub(c1,id1);
    o[1]=cadd(e2,w1d2);  o[5]=csub(e2,w1d2);
    o[3]=cadd(e3,w3d3);  o[7]=csub(e3,w3d3);
}

// steering vector table: [0..CF) = cos(phase)/2, [CF..2CF) = sin(phase)/2
__device__ float g_sv[2 * CF];

// ---------------------------------------------------------------------------
// Prep: TDOA (summed over batch AND coord, per reference) + sv table
// ---------------------------------------------------------------------------
__global__ void __launch_bounds__(1024) prep_kernel(const float* __restrict__ angle,
                                                    const float* __restrict__ mic_pos) {
    __shared__ float tdoa[CC];
    int tid = threadIdx.x;
    if (tid < CC) {
        const float half_pi = (float)(PI_D / 2.0);
        float sin90 = sinf(half_pi);   // fp32 quirks reproduced
        float cos90 = cosf(half_pi);
        float sum = 0.f;
        for (int b = 0; b < BB; b++) {
            float rad = -angle[b] * (float)(PI_D / 180.0);
            float lx = cosf(rad) * sin90;
            float ly = sinf(rad) * sin90;
            float lz = cos90;          // DIST = 1.0
            const float* mp = mic_pos + (b * CC + tid) * 3;
            float dx = mp[0] - lx, dy = mp[1] - ly, dz = mp[2] - lz;
            sum += dx * dx + dy * dy + dz * dz;
        }
        tdoa[tid] = sqrtf(sum);
    }
    __syncthreads();
    const float d0 = tdoa[0];
    const float coef = (float)(-2.0 * PI_D * 16000.0 / (512.0 * 340.4));
    for (int i = tid; i < CF; i += blockDim.x) {
        int c = i / FDIM;
        int f = i - c * FDIM;
        float ph = coef * (float)f * (tdoa[c] - d0);
        float s, co;
        sincosf(ph, &s, &co);
        g_sv[i]      = co * 0.5f;   // sv.real / ||sv||  (norm = sqrt(C) = 2)
        g_sv[CF + i] = s * 0.5f;
    }
}

// ---------------------------------------------------------------------------
// STFT: 256-thread block = 4 FFT units of 64 threads. Each unit computes one
// packed complex FFT (two real channels) for one frame, via 3 radix-8 passes
// (512 = 8^3) with 8 register-resident complex values per thread.
// Also writes the (t-constant) steering-vector feature groups.
// ---------------------------------------------------------------------------
__global__ void __launch_bounds__(256) stft_kernel(const float* __restrict__ x,
                                                   float* __restrict__ out) {
    __shared__ c2 tw[NFFT];        // tw[m] = exp(-2*pi*i*m/512)
    __shared__ c2 sd[4][520];      // skewed: 8 rows of 65 (64 data + 1 pad)

    const int tid = threadIdx.x;

    // twiddle table (2 sincosf per thread)
    for (int m = tid; m < NFFT; m += 256) {
        float ang = (float)(-2.0 * PI_D / (double)NFFT) * (float)m;
        float s, c; sincosf(ang, &s, &c);
        tw[m].x = c; tw[m].y = s;
    }
    __syncthreads();

    const int u   = tid >> 6;        // FFT unit 0..3
    const int tau = tid & 63;        // lane within unit
    const int t   = blockIdx.x * 4 + u;
    const int by  = blockIdx.y;      // b*2 + pair
    const int b   = by >> 1;
    const int pr  = by & 1;          // channel pair: (2pr, 2pr+1)
    const bool active = (t < TT);

    c2 v[8], o8[8];

    // ---- pass 1: load + window, radix-8 over n2, twiddle W64^{n1*k0} ----
    if (active) {
        const float* xa = x + (size_t)(b * CC + 2 * pr) * LSIG;
        const float* xb = xa + LSIG;
#pragma unroll
        for (int n2 = 0; n2 < 8; n2++) {
            int n = n2 * 64 + tau;
            int p = t * HOP + n - 256;                       // reflect pad
            int s = (p < 0) ? -p : ((p >= LSIG) ? 2 * LSIG - 2 - p : p);
            float w = 0.5f * (1.0f - tw[n].x);               // Hann
            v[n2].x = xa[s] * w;
            v[n2].y = xb[s] * w;
        }
        radix8(v, o8);
        int n1 = tau >> 3;
#pragma unroll
        for (int k0 = 0; k0 < 8; k0++) {
            c2 r = cmul(o8[k0], tw[(8 * n1 * k0) & 511]);
            sd[u][k0 * 65 + tau] = r;
        }
    }
    __syncthreads();

    // ---- pass 2: radix-8 over n1, twiddle W512^{n0*(8*k1+k0)} ----
    // thread (k0, n0) reads & writes exactly the addresses {k0*65 + 8*j + n0}:
    // in-place per thread, no barrier needed between its read and write.
    if (active) {
        int k0 = tau >> 3, n0 = tau & 7;
#pragma unroll
        for (int n1 = 0; n1 < 8; n1++) v[n1] = sd[u][k0 * 65 + n1 * 8 + n0];
        radix8(v, o8);
#pragma unroll
        for (int k1 = 0; k1 < 8; k1++) {
            c2 r = cmul(o8[k1], tw[(n0 * (8 * k1 + k0)) & 511]);
            sd[u][k0 * 65 + k1 * 8 + n0] = r;
        }
    }
    __syncthreads();

    // ---- pass 3: radix-8 over n0 -> X[64*k2 + 8*k1 + k0] ----
    if (active) {
        int k0 = tau >> 3, k1 = tau & 7;
#pragma unroll
        for (int n0 = 0; n0 < 8; n0++) v[n0] = sd[u][k0 * 65 + k1 * 8 + n0];
        radix8(v, o8);
    }
    __syncthreads();                 // all pass-2 data consumed before overwrite
    if (active) {
        int k0 = tau >> 3, k1 = tau & 7;
#pragma unroll
        for (int k2 = 0; k2 < 8; k2++) sd[u][k2 * 64 + k1 * 8 + k0] = o8[k2];
    }
    __syncthreads();

    // ---- unpack 2 real spectra + write X groups + SV groups ----
    if (active) {
        float* row = out + ((size_t)b * TT + t) * KFEAT;
        const int ca = 2 * pr, cb = 2 * pr + 1;
        float* aBase = row + ca * FDIM;
        float* bBase = row + cb * FDIM;
        for (int k = tau; k <= 256; k += 64) {
            c2 zk = sd[u][k];
            c2 zm = sd[u][(512 - k) & 511];
            // A = FFT(ch ca), B = FFT(ch cb)
            aBase[k]          = 0.5f * (zk.x + zm.x);   // A.re
            aBase[CF + k]     = 0.5f * (zk.y - zm.y);   // A.im
            bBase[k]          = 0.5f * (zk.y + zm.y);   // B.re
            bBase[CF + k]     = 0.5f * (zm.x - zk.x);   // B.im
            // steering vector (constant over t), groups 2 & 3
            int ia = ca * FDIM + k, ib = cb * FDIM + k;
            aBase[2 * CF + k] = __ldg(&g_sv[ia]);       // sv.re ch ca
            aBase[3 * CF + k] = __ldg(&g_sv[CF + ia]);  // sv.im ch ca
            bBase[2 * CF + k] = __ldg(&g_sv[ib]);       // sv.re ch cb
            bBase[3 * CF + k] = __ldg(&g_sv[CF + ib]);  // sv.im ch cb
        }
    }
}

// ---------------------------------------------------------------------------
extern "C" void kernel_launch(void* const* d_in, const int* in_sizes, int n_in,
                              void* d_out, int out_size) {
    const float* x     = (const float*)d_in[0];
    const float* angle = (const float*)d_in[1];
    const float* mic   = (const float*)d_in[2];
    float* out = (float*)d_out;

    prep_kernel<<<1, 1024>>>(angle, mic);

    dim3 grid((TT + 3) / 4, BB * 2);
    stft_kernel<<<grid, 256>>>(x, out);
}